// round 8
// baseline (speedup 1.0000x reference)
#include <cuda_runtime.h>

// ---------------------------------------------------------------------------
// GCN1: 3x (GCNConv -> BatchNorm -> ReLU[except last]) on N=100000, E=800000
// Output: concat( out[N x 40], x6[N x 512] )
// ---------------------------------------------------------------------------

#define NODES_MAX 100000
#define EDGES_MAX 800000
#define HID 512

// ---- device scratch (allocation-free rule: module globals) ----
__device__ float  g_bufA[NODES_MAX * HID];
__device__ float  g_bufB[NODES_MAX * HID];
__device__ float  g_dinv[NODES_MAX];
__device__ int    g_deg[NODES_MAX];
__device__ int    g_rowptr[NODES_MAX + 1];
__device__ int    g_cursor[NODES_MAX];
__device__ int    g_csrsrc[EDGES_MAX];
__device__ int    g_bsums[256];
__device__ double g_stats[2 * HID];
__device__ float  g_scale[HID];
__device__ float  g_shift[HID];
__device__ int    g_is64;

// ---------------------------------------------------------------------------
// edge dtype sniffing: if the int64 view contains any value outside [0, n),
// the buffer is actually int32 (reinterpreted pairs are huge).
// ---------------------------------------------------------------------------
__global__ void detect_k(const long long* __restrict__ p, int cnt, int n) {
    __shared__ int bad;
    if (threadIdx.x == 0) bad = 0;
    __syncthreads();
    int loc = 0;
    for (int i = threadIdx.x; i < cnt; i += blockDim.x) {
        long long v = p[i];
        if (v < 0 || v >= (long long)n) loc = 1;
    }
    if (loc) bad = 1;
    __syncthreads();
    if (threadIdx.x == 0) g_is64 = bad ? 0 : 1;
}

__global__ void zero_deg_k(int n) {
    int i = blockIdx.x * blockDim.x + threadIdx.x;
    if (i < n) g_deg[i] = 0;
}

__global__ void hist_k(const void* __restrict__ ei, int E) {
    int e = blockIdx.x * blockDim.x + threadIdx.x;
    if (e >= E) return;
    int d;
    if (g_is64) d = (int)((const long long*)ei)[(size_t)E + e];
    else        d = ((const int*)ei)[(size_t)E + e];
    atomicAdd(&g_deg[d], 1);
}

__global__ void dinv_k(int n) {
    int i = blockIdx.x * blockDim.x + threadIdx.x;
    if (i < n) g_dinv[i] = rsqrtf((float)g_deg[i] + 1.0f);
}

// ---- exclusive scan of g_deg into g_rowptr (3 phases) ----
__global__ void scan1_k(int n) {
    __shared__ int sh[1024];
    int tid = threadIdx.x;
    int i = blockIdx.x * 1024 + tid;
    int v = (i < n) ? g_deg[i] : 0;
    sh[tid] = v;
    __syncthreads();
    for (int off = 1; off < 1024; off <<= 1) {
        int t = 0;
        if (tid >= off) t = sh[tid - off];
        __syncthreads();
        sh[tid] += t;
        __syncthreads();
    }
    if (i < n) g_rowptr[i] = sh[tid] - v;      // exclusive
    if (tid == 1023) g_bsums[blockIdx.x] = sh[1023];
}

__global__ void scan2_k(int nb) {
    if (threadIdx.x == 0 && blockIdx.x == 0) {
        int acc = 0;
        for (int i = 0; i < nb; i++) { int t = g_bsums[i]; g_bsums[i] = acc; acc += t; }
    }
}

__global__ void scan3_k(int n, int E) {
    int i = blockIdx.x * blockDim.x + threadIdx.x;
    if (i < n) {
        int r = g_rowptr[i] + g_bsums[i >> 10];
        g_rowptr[i] = r;
        g_cursor[i] = r;
    }
    if (i == 0) g_rowptr[n] = E;
}

__global__ void fill_k(const void* __restrict__ ei, int E) {
    int e = blockIdx.x * blockDim.x + threadIdx.x;
    if (e >= E) return;
    int s, d;
    if (g_is64) {
        const long long* p = (const long long*)ei;
        s = (int)p[e]; d = (int)p[(size_t)E + e];
    } else {
        const int* p = (const int*)ei;
        s = p[e]; d = p[(size_t)E + e];
    }
    int pos = atomicAdd(&g_cursor[d], 1);
    g_csrsrc[pos] = s;
}

// ---------------------------------------------------------------------------
// SGEMM: C[M,N] = dinv[row] * (A[M,K] @ B[K,N])
// 128x128 block tile, BK=8, 256 threads, 8x8 micro-tile, packed f32x2 FMA.
// ---------------------------------------------------------------------------
__global__ void __launch_bounds__(256) sgemm_k(
    const float* __restrict__ A, const float* __restrict__ B,
    float* __restrict__ C, int M, int N, int K)
{
    __shared__ float As[8][128];
    __shared__ float Bs[8][128];

    int tid  = threadIdx.x;
    int brow = blockIdx.y * 128;
    int bcol = blockIdx.x * 128;

    int arow = tid >> 1;            // 0..127
    int acol = (tid & 1) * 4;       // 0 or 4
    int brl  = tid >> 5;            // 0..7
    int bcl  = (tid & 31) * 4;      // 0..124
    int ty   = tid >> 4;            // 0..15
    int tx   = tid & 15;            // 0..15

    unsigned long long acc[8][4];
#pragma unroll
    for (int i = 0; i < 8; i++)
#pragma unroll
        for (int j = 0; j < 4; j++) acc[i][j] = 0ull;

    int grow = brow + arow;

    for (int k0 = 0; k0 < K; k0 += 8) {
        // load A tile (128x8), store transposed
        float4 av = make_float4(0.f, 0.f, 0.f, 0.f);
        if (grow < M) av = __ldg((const float4*)(A + (size_t)grow * K + k0 + acol));
        As[acol + 0][arow] = av.x;
        As[acol + 1][arow] = av.y;
        As[acol + 2][arow] = av.z;
        As[acol + 3][arow] = av.w;

        // load B tile (8x128)
        int gcol = bcol + bcl;
        float4 bv;
        if (gcol + 3 < N) {
            bv = __ldg((const float4*)(B + (size_t)(k0 + brl) * N + gcol));
        } else {
            float t0 = 0.f, t1 = 0.f, t2 = 0.f, t3 = 0.f;
            const float* brp = B + (size_t)(k0 + brl) * N;
            if (gcol + 0 < N) t0 = brp[gcol + 0];
            if (gcol + 1 < N) t1 = brp[gcol + 1];
            if (gcol + 2 < N) t2 = brp[gcol + 2];
            if (gcol + 3 < N) t3 = brp[gcol + 3];
            bv = make_float4(t0, t1, t2, t3);
        }
        *(float4*)&Bs[brl][bcl] = bv;
        __syncthreads();

#pragma unroll
        for (int k = 0; k < 8; k++) {
            float4 a0 = *(const float4*)&As[k][ty * 8];
            float4 a1 = *(const float4*)&As[k][ty * 8 + 4];
            ulonglong2 bA = *(const ulonglong2*)&Bs[k][tx * 8];
            ulonglong2 bB = *(const ulonglong2*)&Bs[k][tx * 8 + 4];
            float avv[8] = {a0.x, a0.y, a0.z, a0.w, a1.x, a1.y, a1.z, a1.w};
            unsigned long long bb[4] = {bA.x, bA.y, bB.x, bB.y};
#pragma unroll
            for (int i = 0; i < 8; i++) {
                unsigned long long ad;
                asm("mov.b64 %0, {%1, %1};" : "=l"(ad) : "r"(__float_as_uint(avv[i])));
#pragma unroll
                for (int jp = 0; jp < 4; jp++)
                    asm("fma.rn.f32x2 %0, %1, %2, %0;"
                        : "+l"(acc[i][jp]) : "l"(ad), "l"(bb[jp]));
            }
        }
        __syncthreads();
    }

    // epilogue: scale by dinv[row], guarded stores
#pragma unroll
    for (int i = 0; i < 8; i++) {
        int r = brow + ty * 8 + i;
        if (r >= M) continue;
        float sc = g_dinv[r];
#pragma unroll
        for (int jp = 0; jp < 4; jp++) {
            int c = bcol + tx * 8 + jp * 2;
            unsigned long long v = acc[i][jp];
            float lo = __uint_as_float((unsigned)v) * sc;
            float hi = __uint_as_float((unsigned)(v >> 32)) * sc;
            if (c + 1 < N) {
                *(float2*)(C + (size_t)r * N + c) = make_float2(lo, hi);
            } else if (c < N) {
                C[(size_t)r * N + c] = lo;
            }
        }
    }
}

// ---------------------------------------------------------------------------
// Aggregation: y[d] = dinv[d] * ( sum_{e: dst=d} hs[src_e] + hs[d] ) + bias
// One block per node, float4 per thread, CSR gather (no atomics).
// ---------------------------------------------------------------------------
__global__ void agg_k(const float* __restrict__ hs, float* __restrict__ y,
                      const float* __restrict__ bias, int F4)
{
    int node = blockIdx.x;
    int tid = threadIdx.x;
    if (tid >= F4) return;
    const float4* hv = (const float4*)hs;

    float4 acc = __ldg(&hv[(size_t)node * F4 + tid]);   // self term
    int e  = g_rowptr[node];
    int e1 = g_rowptr[node + 1];
    for (; e + 1 < e1; e += 2) {
        int s0 = g_csrsrc[e];
        int s1 = g_csrsrc[e + 1];
        float4 v0 = __ldg(&hv[(size_t)s0 * F4 + tid]);
        float4 v1 = __ldg(&hv[(size_t)s1 * F4 + tid]);
        acc.x += v0.x + v1.x; acc.y += v0.y + v1.y;
        acc.z += v0.z + v1.z; acc.w += v0.w + v1.w;
    }
    if (e < e1) {
        int s = g_csrsrc[e];
        float4 v = __ldg(&hv[(size_t)s * F4 + tid]);
        acc.x += v.x; acc.y += v.y; acc.z += v.z; acc.w += v.w;
    }
    float d = g_dinv[node];
    float4 bb = __ldg(&((const float4*)bias)[tid]);
    float4 o;
    o.x = fmaf(acc.x, d, bb.x);
    o.y = fmaf(acc.y, d, bb.y);
    o.z = fmaf(acc.z, d, bb.z);
    o.w = fmaf(acc.w, d, bb.w);
    ((float4*)y)[(size_t)node * F4 + tid] = o;
}

// ---------------------------------------------------------------------------
// BatchNorm statistics (double accumulation) + affine finalize + apply
// ---------------------------------------------------------------------------
__global__ void zero_stats_k() { g_stats[threadIdx.x] = 0.0; }

__global__ void stats_k(const float* __restrict__ y, int n, int F) {
    int f = threadIdx.x;
    if (f >= F) return;
    double s = 0.0, ss = 0.0;
    for (int r = blockIdx.x; r < n; r += gridDim.x) {
        float v = y[(size_t)r * F + f];
        s += (double)v;
        ss += (double)v * (double)v;
    }
    atomicAdd(&g_stats[f], s);
    atomicAdd(&g_stats[F + f], ss);
}

__global__ void finalize_k(const float* __restrict__ gam,
                           const float* __restrict__ bet, int n, int F) {
    int f = threadIdx.x;
    if (f >= F) return;
    double mean = g_stats[f] / (double)n;
    double var  = g_stats[F + f] / (double)n - mean * mean;
    float is = rsqrtf((float)var + 1e-5f);
    float sc = gam[f] * is;
    g_scale[f] = sc;
    g_shift[f] = bet[f] - (float)mean * sc;
}

__global__ void norm_k(const float* __restrict__ y, float* __restrict__ o,
                       int F, int do_relu) {
    int node = blockIdx.x;
    for (int f = threadIdx.x; f < F; f += blockDim.x) {
        float v = g_scale[f] * y[(size_t)node * F + f] + g_shift[f];
        if (do_relu) v = fmaxf(v, 0.0f);
        o[(size_t)node * F + f] = v;
    }
}

// ---------------------------------------------------------------------------
// host launch
// ---------------------------------------------------------------------------
extern "C" void kernel_launch(void* const* d_in, const int* in_sizes, int n_in,
                              void* d_out, int out_size)
{
    const float* x    = (const float*)d_in[0];
    const void*  ei   = d_in[1];
    const float* W1   = (const float*)d_in[2];
    const float* b1   = (const float*)d_in[3];
    const float* ga1  = (const float*)d_in[4];
    const float* be1  = (const float*)d_in[5];
    const float* W2   = (const float*)d_in[6];
    const float* b2   = (const float*)d_in[7];
    const float* ga2  = (const float*)d_in[8];
    const float* be2  = (const float*)d_in[9];
    const float* W3   = (const float*)d_in[10];
    const float* b3   = (const float*)d_in[11];
    const float* ga3  = (const float*)d_in[12];
    const float* be3  = (const float*)d_in[13];

    int n = in_sizes[0] / 128;   // 100000
    int E = in_sizes[1] / 2;     // 800000

    float* out = (float*)d_out;             // [n, 40]
    float* x6  = out + (size_t)n * 40;      // [n, 512]

    float *bufA, *bufB;
    cudaGetSymbolAddress((void**)&bufA, g_bufA);
    cudaGetSymbolAddress((void**)&bufB, g_bufB);

    const int T = 256;
    int gbN = (n + T - 1) / T;
    int gbE = (E + T - 1) / T;
    int nb1024 = (n + 1023) / 1024;

    // graph prep: degrees, dinv, CSR
    detect_k<<<1, 256>>>((const long long*)ei, (E < 4096 ? E : 4096), n);
    zero_deg_k<<<gbN, T>>>(n);
    hist_k<<<gbE, T>>>(ei, E);
    dinv_k<<<gbN, T>>>(n);
    scan1_k<<<nb1024, 1024>>>(n);
    scan2_k<<<1, 32>>>(nb1024);
    scan3_k<<<gbN, T>>>(n, E);
    fill_k<<<gbE, T>>>(ei, E);

    dim3 gemm_big((512 + 127) / 128, (n + 127) / 128);
    dim3 gemm_sm ((40  + 127) / 128, (n + 127) / 128);

    // ---- Layer 1: x[n,128] -> bufA(hs) -> bufB(y) -> BN+ReLU -> bufA(x3) ----
    sgemm_k<<<gemm_big, 256>>>(x, W1, bufA, n, 512, 128);
    agg_k<<<n, 128>>>(bufA, bufB, b1, 128);
    zero_stats_k<<<1, 1024>>>();
    stats_k<<<256, 512>>>(bufB, n, 512);
    finalize_k<<<1, 512>>>(ga1, be1, n, 512);
    norm_k<<<n, 128>>>(bufB, bufA, 512, 1);

    // ---- Layer 2: bufA -> bufB(hs) -> bufA(y) -> BN+ReLU -> x6 (d_out) ----
    sgemm_k<<<gemm_big, 256>>>(bufA, W2, bufB, n, 512, 512);
    agg_k<<<n, 128>>>(bufB, bufA, b2, 128);
    zero_stats_k<<<1, 1024>>>();
    stats_k<<<256, 512>>>(bufA, n, 512);
    finalize_k<<<1, 512>>>(ga2, be2, n, 512);
    norm_k<<<n, 128>>>(bufA, x6, 512, 1);

    // ---- Layer 3: x6 -> bufA(hs[n,40]) -> bufB(y) -> BN (no ReLU) -> out ----
    sgemm_k<<<gemm_sm, 256>>>(x6, W3, bufA, n, 40, 512);
    agg_k<<<n, 32>>>(bufA, bufB, b3, 10);
    zero_stats_k<<<1, 1024>>>();
    stats_k<<<256, 64>>>(bufB, n, 40);
    finalize_k<<<1, 64>>>(ga3, be3, n, 40);
    norm_k<<<n, 64>>>(bufB, out, 40, 0);
}

// round 12
// speedup vs baseline: 1.7224x; 1.7224x over previous
#include <cuda_runtime.h>
#include <cuda_bf16.h>
#include <cstdint>

// ---------------------------------------------------------------------------
// GCN1: 3x (GCNConv -> BatchNorm -> ReLU[except last]) on N=100000, E=800000
// Output: concat( out[N x 40], x6[N x 512] )
//
// Pipeline (aggregate on the narrow side; GEMMs via mma.sync bf16-split):
//   L1: u = agg(x)[128]   -> h = uW1+b1 -> BN+ReLU -> x3
//   L2: u = agg(x3)[512]  -> h = uW2+b2 -> BN+ReLU -> x6 (+bf16 split)
//   L3: h = x6W3 [40]     -> y = agg(h)+b3 -> BN   -> out
// GEMM numerics: A,B split into bf16 (hi, lo); acc += Ah*Bh + Ah*Bl + Al*Bh
// in fp32 (dropped ll term ~2^-16).
// ---------------------------------------------------------------------------

#define NODES_MAX 100000
#define EDGES_MAX 800000
#define HID 512

// ---- device scratch ----
__device__ __nv_bfloat16 g_uh[NODES_MAX * HID];
__device__ __nv_bfloat16 g_ul[NODES_MAX * HID];
__device__ float  g_h [NODES_MAX * HID];
__device__ float  g_t [NODES_MAX * HID];
__device__ __nv_bfloat16 g_wh[HID * HID];   // transposed: [nb][K]
__device__ __nv_bfloat16 g_wl[HID * HID];
__device__ float  g_dinv[NODES_MAX];
__device__ int    g_deg[NODES_MAX];
__device__ int    g_rowptr[NODES_MAX + 1];
__device__ int    g_cursor[NODES_MAX];
__device__ int    g_csrsrc[EDGES_MAX];
__device__ int    g_bsums[256];
__device__ double g_stats[2 * HID];
__device__ float  g_scale[HID];
__device__ float  g_shift[HID];
__device__ int    g_is64;

__device__ __forceinline__ void split_bf16(float v, __nv_bfloat16& h, __nv_bfloat16& l) {
    h = __float2bfloat16(v);
    l = __float2bfloat16(v - __bfloat162float(h));
}

// mma.sync m16n8k16 bf16 x bf16 -> f32 (PTX ISA 7.0, sm_80+, no 'a' features)
__device__ __forceinline__ void mma_bf16(float (&c)[4],
                                         const uint32_t (&a)[4],
                                         const uint32_t (&b)[2]) {
    asm volatile(
        "mma.sync.aligned.m16n8k16.row.col.f32.bf16.bf16.f32 "
        "{%0,%1,%2,%3}, {%4,%5,%6,%7}, {%8,%9}, {%0,%1,%2,%3};"
        : "+f"(c[0]), "+f"(c[1]), "+f"(c[2]), "+f"(c[3])
        : "r"(a[0]), "r"(a[1]), "r"(a[2]), "r"(a[3]), "r"(b[0]), "r"(b[1]));
}

// ===========================================================================
// Graph prep (CSR by dst, dinv) — proven in round 7
// ===========================================================================
__global__ void detect_k(const long long* __restrict__ p, int cnt, int n) {
    __shared__ int bad;
    if (threadIdx.x == 0) bad = 0;
    __syncthreads();
    int loc = 0;
    for (int i = threadIdx.x; i < cnt; i += blockDim.x) {
        long long v = p[i];
        if (v < 0 || v >= (long long)n) loc = 1;
    }
    if (loc) bad = 1;
    __syncthreads();
    if (threadIdx.x == 0) g_is64 = bad ? 0 : 1;
}
__global__ void zero_deg_k(int n) {
    int i = blockIdx.x * blockDim.x + threadIdx.x;
    if (i < n) g_deg[i] = 0;
}
__global__ void hist_k(const void* __restrict__ ei, int E) {
    int e = blockIdx.x * blockDim.x + threadIdx.x;
    if (e >= E) return;
    int d;
    if (g_is64) d = (int)((const long long*)ei)[(size_t)E + e];
    else        d = ((const int*)ei)[(size_t)E + e];
    atomicAdd(&g_deg[d], 1);
}
__global__ void dinv_k(int n) {
    int i = blockIdx.x * blockDim.x + threadIdx.x;
    if (i < n) g_dinv[i] = rsqrtf((float)g_deg[i] + 1.0f);
}
__global__ void scan1_k(int n) {
    __shared__ int sh[1024];
    int tid = threadIdx.x;
    int i = blockIdx.x * 1024 + tid;
    int v = (i < n) ? g_deg[i] : 0;
    sh[tid] = v;
    __syncthreads();
    for (int off = 1; off < 1024; off <<= 1) {
        int t = 0;
        if (tid >= off) t = sh[tid - off];
        __syncthreads();
        sh[tid] += t;
        __syncthreads();
    }
    if (i < n) g_rowptr[i] = sh[tid] - v;
    if (tid == 1023) g_bsums[blockIdx.x] = sh[1023];
}
__global__ void scan2_k(int nb) {
    if (threadIdx.x == 0 && blockIdx.x == 0) {
        int acc = 0;
        for (int i = 0; i < nb; i++) { int t = g_bsums[i]; g_bsums[i] = acc; acc += t; }
    }
}
__global__ void scan3_k(int n, int E) {
    int i = blockIdx.x * blockDim.x + threadIdx.x;
    if (i < n) {
        int r = g_rowptr[i] + g_bsums[i >> 10];
        g_rowptr[i] = r;
        g_cursor[i] = r;
    }
    if (i == 0) g_rowptr[n] = E;
}
__global__ void fill_k(const void* __restrict__ ei, int E) {
    int e = blockIdx.x * blockDim.x + threadIdx.x;
    if (e >= E) return;
    int s, d;
    if (g_is64) {
        const long long* p = (const long long*)ei;
        s = (int)p[e]; d = (int)p[(size_t)E + e];
    } else {
        const int* p = (const int*)ei;
        s = p[e]; d = p[(size_t)E + e];
    }
    int pos = atomicAdd(&g_cursor[d], 1);
    g_csrsrc[pos] = s;
}

// ===========================================================================
// Weight convert: g_wh/g_wl[nb*K+k] = split( W[k*N+nb] ), zero-pad nb>=N
// (transposed layout = exactly the mma.sync "col" B operand, K contiguous)
// ===========================================================================
__global__ void wconv_k(const float* __restrict__ W, int K, int N, int NB) {
    int i = blockIdx.x * blockDim.x + threadIdx.x;
    if (i >= NB * K) return;
    int nb = i / K, k = i - nb * K;
    float v = (nb < N) ? W[(size_t)k * N + nb] : 0.0f;
    __nv_bfloat16 h, l;
    split_bf16(v, h, l);
    g_wh[i] = h;
    g_wl[i] = l;
}

// ===========================================================================
// Aggregation (CSR gather): u_d = dinv_d * ( sum_e dinv_s*in_s + dinv_d*in_d )
// Variant A: emits bf16 hi/lo (GEMM operand). Variant B: fp32 + bias (L3).
// ===========================================================================
__global__ void agg_split_k(const float* __restrict__ in,
                            __nv_bfloat16* __restrict__ oh,
                            __nv_bfloat16* __restrict__ ol, int F4) {
    int node = blockIdx.x;
    int tid = threadIdx.x;
    if (tid >= F4) return;
    const float4* iv = (const float4*)in;
    float dd = g_dinv[node];
    float4 sv = __ldg(&iv[(size_t)node * F4 + tid]);
    float4 acc = make_float4(sv.x * dd, sv.y * dd, sv.z * dd, sv.w * dd);
    int e = g_rowptr[node], e1 = g_rowptr[node + 1];
    for (; e + 1 < e1; e += 2) {
        int s0 = g_csrsrc[e], s1 = g_csrsrc[e + 1];
        float d0 = g_dinv[s0], d1 = g_dinv[s1];
        float4 v0 = __ldg(&iv[(size_t)s0 * F4 + tid]);
        float4 v1 = __ldg(&iv[(size_t)s1 * F4 + tid]);
        acc.x += v0.x * d0 + v1.x * d1;
        acc.y += v0.y * d0 + v1.y * d1;
        acc.z += v0.z * d0 + v1.z * d1;
        acc.w += v0.w * d0 + v1.w * d1;
    }
    if (e < e1) {
        int s = g_csrsrc[e];
        float ds = g_dinv[s];
        float4 v = __ldg(&iv[(size_t)s * F4 + tid]);
        acc.x += v.x * ds; acc.y += v.y * ds; acc.z += v.z * ds; acc.w += v.w * ds;
    }
    acc.x *= dd; acc.y *= dd; acc.z *= dd; acc.w *= dd;

    __nv_bfloat16 h0, l0, h1, l1, h2, l2, h3, l3;
    split_bf16(acc.x, h0, l0); split_bf16(acc.y, h1, l1);
    split_bf16(acc.z, h2, l2); split_bf16(acc.w, h3, l3);
    size_t base = ((size_t)node * F4 + tid) * 4;
    uint2 ph, pl;
    ph.x = (uint32_t)__bfloat16_as_ushort(h0) | ((uint32_t)__bfloat16_as_ushort(h1) << 16);
    ph.y = (uint32_t)__bfloat16_as_ushort(h2) | ((uint32_t)__bfloat16_as_ushort(h3) << 16);
    pl.x = (uint32_t)__bfloat16_as_ushort(l0) | ((uint32_t)__bfloat16_as_ushort(l1) << 16);
    pl.y = (uint32_t)__bfloat16_as_ushort(l2) | ((uint32_t)__bfloat16_as_ushort(l3) << 16);
    *(uint2*)(oh + base) = ph;
    *(uint2*)(ol + base) = pl;
}

__global__ void agg_f32_k(const float* __restrict__ in, float* __restrict__ out,
                          const float* __restrict__ bias, int F4) {
    int node = blockIdx.x;
    int tid = threadIdx.x;
    if (tid >= F4) return;
    const float4* iv = (const float4*)in;
    float dd = g_dinv[node];
    float4 sv = __ldg(&iv[(size_t)node * F4 + tid]);
    float4 acc = make_float4(sv.x * dd, sv.y * dd, sv.z * dd, sv.w * dd);
    int e = g_rowptr[node], e1 = g_rowptr[node + 1];
    for (; e < e1; e++) {
        int s = g_csrsrc[e];
        float ds = g_dinv[s];
        float4 v = __ldg(&iv[(size_t)s * F4 + tid]);
        acc.x += v.x * ds; acc.y += v.y * ds; acc.z += v.z * ds; acc.w += v.w * ds;
    }
    float4 bb = __ldg(&((const float4*)bias)[tid]);
    float4 o;
    o.x = fmaf(acc.x, dd, bb.x);
    o.y = fmaf(acc.y, dd, bb.y);
    o.z = fmaf(acc.z, dd, bb.z);
    o.w = fmaf(acc.w, dd, bb.w);
    ((float4*)out)[(size_t)node * F4 + tid] = o;
}

// ===========================================================================
// Tensor-core GEMM (mma.sync m16n8k16 bf16-split):
//   C[M x NOUT] = A[M x K] @ B^T, B stored [NB x K] (n-major), + bias
// CTA tile: 128 x (NWARPN*32). Warp tile 32x32 (mfrags=2, nfrags=4).
// A staged in smem (pad 72 -> conflict-free lds); B register-direct from L1/L2.
// ===========================================================================
template <int NWARPN>
__global__ void __launch_bounds__(NWARPN * 128, 1) gemm_mma_k(
    const __nv_bfloat16* __restrict__ Ah, const __nv_bfloat16* __restrict__ Al,
    const __nv_bfloat16* __restrict__ Bh, const __nv_bfloat16* __restrict__ Bl,
    float* __restrict__ C, const float* __restrict__ bias,
    int M, int K, int NOUT)
{
    __shared__ __nv_bfloat16 sAh[128][72];
    __shared__ __nv_bfloat16 sAl[128][72];

    const int tid  = threadIdx.x;
    const int lane = tid & 31;
    const int wid  = tid >> 5;
    const int mw   = wid & 3;       // 0..3 (m-warp)
    const int nw   = wid >> 2;      // 0..NWARPN-1 (n-warp)
    const int lq   = lane >> 2;     // 0..7
    const int lr   = lane & 3;      // 0..3
    const int row0 = blockIdx.x * 128;
    const int col0 = blockIdx.y * (NWARPN * 32);

    float acc[2][4][4];
#pragma unroll
    for (int a = 0; a < 2; a++)
#pragma unroll
        for (int b = 0; b < 4; b++)
#pragma unroll
            for (int c = 0; c < 4; c++) acc[a][b][c] = 0.f;

    // per-thread B base pointers (fragment: two bf16 at consecutive k)
    const int bcol = col0 + nw * 32 + lq;
    const __nv_bfloat16* bph = Bh + (size_t)bcol * K + lr * 2;
    const __nv_bfloat16* bpl = Bl + (size_t)bcol * K + lr * 2;

    for (int k0 = 0; k0 < K; k0 += 64) {
        if (k0) __syncthreads();
        // stage A (128 x 64) hi+lo
        for (int s = tid; s < 1024; s += NWARPN * 128) {
            int r = s >> 3, c8 = (s & 7) << 3;
            int gr = row0 + r;
            uint4 vh = make_uint4(0, 0, 0, 0), vl = make_uint4(0, 0, 0, 0);
            if (gr < M) {
                vh = __ldg((const uint4*)(Ah + (size_t)gr * K + k0 + c8));
                vl = __ldg((const uint4*)(Al + (size_t)gr * K + k0 + c8));
            }
            *(uint4*)&sAh[r][c8] = vh;
            *(uint4*)&sAl[r][c8] = vl;
        }
        __syncthreads();

#pragma unroll
        for (int ks = 0; ks < 4; ks++) {
            const int kk = ks * 16;
            uint32_t ah[2][4], al[2][4];
#pragma unroll
            for (int mf = 0; mf < 2; mf++) {
                int r = mw * 32 + mf * 16 + lq;
                int c = kk + lr * 2;
                ah[mf][0] = *(const uint32_t*)&sAh[r][c];
                ah[mf][1] = *(const uint32_t*)&sAh[r + 8][c];
                ah[mf][2] = *(const uint32_t*)&sAh[r][c + 8];
                ah[mf][3] = *(const uint32_t*)&sAh[r + 8][c + 8];
                al[mf][0] = *(const uint32_t*)&sAl[r][c];
                al[mf][1] = *(const uint32_t*)&sAl[r + 8][c];
                al[mf][2] = *(const uint32_t*)&sAl[r][c + 8];
                al[mf][3] = *(const uint32_t*)&sAl[r + 8][c + 8];
            }
#pragma unroll
            for (int nf = 0; nf < 4; nf++) {
                const size_t off = (size_t)nf * 8 * K + k0 + kk;
                uint32_t bh[2], bl[2];
                bh[0] = *(const uint32_t*)(bph + off);
                bh[1] = *(const uint32_t*)(bph + off + 8);
                bl[0] = *(const uint32_t*)(bpl + off);
                bl[1] = *(const uint32_t*)(bpl + off + 8);
#pragma unroll
                for (int mf = 0; mf < 2; mf++) {
                    mma_bf16(acc[mf][nf], ah[mf], bh);   // hh
                    mma_bf16(acc[mf][nf], ah[mf], bl);   // hl
                    mma_bf16(acc[mf][nf], al[mf], bh);   // lh
                }
            }
        }
    }

    // epilogue: + bias, fp32 store (cc even, NOUT even -> float2 safe)
#pragma unroll
    for (int mf = 0; mf < 2; mf++) {
        int r = row0 + mw * 32 + mf * 16 + lq;
#pragma unroll
        for (int nf = 0; nf < 4; nf++) {
            int cc = col0 + nw * 32 + nf * 8 + lr * 2;
            if (cc < NOUT) {
                float2 bb = bias ? *(const float2*)(bias + cc)
                                 : make_float2(0.f, 0.f);
                if (r < M)
                    *(float2*)(C + (size_t)r * NOUT + cc) =
                        make_float2(acc[mf][nf][0] + bb.x, acc[mf][nf][1] + bb.y);
                if (r + 8 < M)
                    *(float2*)(C + (size_t)(r + 8) * NOUT + cc) =
                        make_float2(acc[mf][nf][2] + bb.x, acc[mf][nf][3] + bb.y);
            }
        }
    }
}

// ===========================================================================
// BatchNorm: float partial sums -> double atomics; finalize; apply (+split)
// ===========================================================================
__global__ void zero_stats_k() { g_stats[threadIdx.x] = 0.0; }

__global__ void stats_k(const float* __restrict__ y, int n, int F) {
    int f = threadIdx.x;
    if (f >= F) return;
    float s = 0.f, ss = 0.f;
    for (int r = blockIdx.x; r < n; r += gridDim.x) {
        float v = y[(size_t)r * F + f];
        s += v;
        ss = fmaf(v, v, ss);
    }
    atomicAdd(&g_stats[f], (double)s);
    atomicAdd(&g_stats[F + f], (double)ss);
}

__global__ void finalize_k(const float* __restrict__ gam,
                           const float* __restrict__ bet, int n, int F) {
    int f = threadIdx.x;
    if (f >= F) return;
    double mean = g_stats[f] / (double)n;
    double var  = g_stats[F + f] / (double)n - mean * mean;
    float is = rsqrtf((float)var + 1e-5f);
    float sc = gam[f] * is;
    g_scale[f] = sc;
    g_shift[f] = bet[f] - (float)mean * sc;
}

__global__ void norm_k(const float* __restrict__ y, float* __restrict__ of,
                       __nv_bfloat16* __restrict__ oh, __nv_bfloat16* __restrict__ ol,
                       int F, int do_relu) {
    int node = blockIdx.x;
    for (int f = threadIdx.x; f < F; f += blockDim.x) {
        float v = fmaf(g_scale[f], y[(size_t)node * F + f], g_shift[f]);
        if (do_relu) v = fmaxf(v, 0.0f);
        if (of) of[(size_t)node * F + f] = v;
        if (oh) {
            __nv_bfloat16 h, l;
            split_bf16(v, h, l);
            oh[(size_t)node * F + f] = h;
            ol[(size_t)node * F + f] = l;
        }
    }
}

// ===========================================================================
// host launch
// ===========================================================================
extern "C" void kernel_launch(void* const* d_in, const int* in_sizes, int n_in,
                              void* d_out, int out_size)
{
    const float* x   = (const float*)d_in[0];
    const void*  ei  = d_in[1];
    const float* W1  = (const float*)d_in[2];
    const float* b1  = (const float*)d_in[3];
    const float* ga1 = (const float*)d_in[4];
    const float* be1 = (const float*)d_in[5];
    const float* W2  = (const float*)d_in[6];
    const float* b2  = (const float*)d_in[7];
    const float* ga2 = (const float*)d_in[8];
    const float* be2 = (const float*)d_in[9];
    const float* W3  = (const float*)d_in[10];
    const float* b3  = (const float*)d_in[11];
    const float* ga3 = (const float*)d_in[12];
    const float* be3 = (const float*)d_in[13];

    int n = in_sizes[0] / 128;   // 100000
    int E = in_sizes[1] / 2;     // 800000

    float* out = (float*)d_out;             // [n, 40]
    float* x6  = out + (size_t)n * 40;      // [n, 512]

    __nv_bfloat16 *uh, *ul, *wh, *wl;
    float *hbuf, *tbuf;
    cudaGetSymbolAddress((void**)&uh, g_uh);
    cudaGetSymbolAddress((void**)&ul, g_ul);
    cudaGetSymbolAddress((void**)&wh, g_wh);
    cudaGetSymbolAddress((void**)&wl, g_wl);
    cudaGetSymbolAddress((void**)&hbuf, g_h);
    cudaGetSymbolAddress((void**)&tbuf, g_t);

    const int T = 256;
    int gbN = (n + T - 1) / T;
    int gbE = (E + T - 1) / T;
    int nb1024 = (n + 1023) / 1024;
    int gtiles = (n + 127) / 128;

    // ---- graph prep ----
    detect_k<<<1, 256>>>((const long long*)ei, (E < 4096 ? E : 4096), n);
    zero_deg_k<<<gbN, T>>>(n);
    hist_k<<<gbE, T>>>(ei, E);
    dinv_k<<<gbN, T>>>(n);
    scan1_k<<<nb1024, 1024>>>(n);
    scan2_k<<<1, 32>>>(nb1024);
    scan3_k<<<gbN, T>>>(n, E);
    fill_k<<<gbE, T>>>(ei, E);

    // ---- Layer 1: agg(x)[128] -> GEMM(K=128, N=512) -> BN+ReLU -> tbuf ----
    wconv_k<<<(512 * 128 + 255) / 256, 256>>>(W1, 128, 512, 512);
    agg_split_k<<<n, 32>>>(x, uh, ul, 32);
    gemm_mma_k<4><<<dim3(gtiles, 4), 512>>>(uh, ul, wh, wl, hbuf, b1,
                                            n, 128, 512);
    zero_stats_k<<<1, 1024>>>();
    stats_k<<<256, 512>>>(hbuf, n, 512);
    finalize_k<<<1, 512>>>(ga1, be1, n, 512);
    norm_k<<<n, 128>>>(hbuf, tbuf, nullptr, nullptr, 512, 1);

    // ---- Layer 2: agg(x3)[512] -> GEMM(K=512, N=512) -> BN+ReLU -> x6 ----
    wconv_k<<<(512 * 512 + 255) / 256, 256>>>(W2, 512, 512, 512);
    agg_split_k<<<n, 128>>>(tbuf, uh, ul, 128);
    gemm_mma_k<4><<<dim3(gtiles, 4), 512>>>(uh, ul, wh, wl, hbuf, b2,
                                            n, 512, 512);
    zero_stats_k<<<1, 1024>>>();
    stats_k<<<256, 512>>>(hbuf, n, 512);
    finalize_k<<<1, 512>>>(ga2, be2, n, 512);
    norm_k<<<n, 128>>>(hbuf, x6, uh, ul, 512, 1);

    // ---- Layer 3: GEMM(x6)[K=512, N=40(pad 64)] -> agg(+b3) -> BN -> out ----
    wconv_k<<<(64 * 512 + 255) / 256, 256>>>(W3, 512, 40, 64);
    gemm_mma_k<2><<<dim3(gtiles, 1), 256>>>(uh, ul, wh, wl, tbuf, nullptr,
                                            n, 512, 40);
    agg_f32_k<<<n, 32>>>(tbuf, hbuf, b3, 10);
    zero_stats_k<<<1, 1024>>>();
    stats_k<<<256, 64>>>(hbuf, n, 40);
    finalize_k<<<1, 64>>>(ga3, be3, n, 40);
    norm_k<<<n, 64>>>(hbuf, out, nullptr, nullptr, 40, 0);
}